// round 14
// baseline (speedup 1.0000x reference)
#include <cuda_runtime.h>
#include <cuda_fp16.h>
#include <math.h>
#include <cstdint>

#define NHIST 24
#define NFORE 20
#define MT    64
#define NTH   256
#define ASTR  264     // sAct row stride (fp16 elems)

// ---------------- prepped weights: fragment-major fp16 ----------------
__device__ __align__(16) unsigned char gW1f[24576];    // 3 ks x 16 nb x 512
__device__ __align__(16) unsigned char gW2f[131072];   // 16 x 16 x 512
__device__ __align__(16) unsigned char gW3f[131072];
__device__ __align__(16) unsigned char gW4f[16384];    // 16 ks x 4 no x 256

// ---------------- SMEM layout (bytes) ----------------
#define A_OFF    0          // 64*264*2 = 33792
#define PHYS_OFF 33792      // 64*20*4 = 5120
#define BIAS_OFF 38912      // 768*4 = 3072
#define B4_OFF   41984      // 128
#define SMEM_TOTAL 42112

// ---------------- PTX helpers ----------------
__device__ __forceinline__ uint32_t smem_u32(const void* p) {
    uint32_t a;
    asm("{ .reg .u64 t; cvta.to.shared.u64 t, %1; cvt.u32.u64 %0, t; }" : "=r"(a) : "l"(p));
    return a;
}
__device__ __forceinline__ void ldm4(uint32_t r[4], uint32_t a) {
    asm volatile("ldmatrix.sync.aligned.m8n8.x4.shared.b16 {%0,%1,%2,%3}, [%4];"
                 : "=r"(r[0]), "=r"(r[1]), "=r"(r[2]), "=r"(r[3]) : "r"(a));
}
__device__ __forceinline__ void mmah(float c[4], const uint32_t a[4], const uint32_t b[2]) {
    asm volatile("mma.sync.aligned.m16n8k16.row.col.f32.f16.f16.f32 "
                 "{%0,%1,%2,%3}, {%4,%5,%6,%7}, {%8,%9}, {%0,%1,%2,%3};"
                 : "+f"(c[0]), "+f"(c[1]), "+f"(c[2]), "+f"(c[3])
                 : "r"(a[0]), "r"(a[1]), "r"(a[2]), "r"(a[3]), "r"(b[0]), "r"(b[1]));
}
__device__ __forceinline__ float tanha(float x) {
    float r; asm("tanh.approx.f32 %0, %1;" : "=f"(r) : "f"(x)); return r;
}
__device__ __forceinline__ uint32_t packh2(float lo, float hi) {
    __half2 t = __floats2half2_rn(lo, hi);
    return *reinterpret_cast<uint32_t*>(&t);
}
// group-local barrier: 128 threads of wm-group (barrier id 1 or 2)
__device__ __forceinline__ void gbar(int wm) {
    asm volatile("bar.sync %0, %1;" :: "r"(wm + 1), "r"(128) : "memory");
}

// ---------------- weight prep: fragment-major emit ----------------
__global__ void prep_kernel(const float* __restrict__ w1, const float* __restrict__ w2,
                            const float* __restrict__ w3, const float* __restrict__ w4)
{
    int idx = blockIdx.x * blockDim.x + threadIdx.x;
    int stride = gridDim.x * blockDim.x;

    for (int u = idx; u < 3 * 16 * 32; u += stride) {       // W1 [44x256]
        int lane = u & 31, frag = u >> 5;
        int ks = frag >> 4, nb = frag & 15;
        __half h[8];
        #pragma unroll
        for (int j = 0; j < 8; j++) {
            int jj = j & 3;
            int kk = ks * 16 + ((jj >> 1) * 8) + 2 * (lane & 3) + (jj & 1);
            int nn = nb * 16 + (lane >> 2) + ((j >> 2) * 8);
            float v = (kk < 44) ? w1[kk * 256 + nn] : 0.0f;
            h[j] = __float2half_rn(v);
        }
        *(uint4*)(gW1f + (size_t)frag * 512 + (size_t)lane * 16) = *(uint4*)h;
    }
    for (int u = idx; u < 16 * 16 * 32; u += stride) {      // W2, W3 [256x256]
        int lane = u & 31, frag = u >> 5;
        int ks = frag >> 4, nb = frag & 15;
        __half h2v[8], h3v[8];
        #pragma unroll
        for (int j = 0; j < 8; j++) {
            int jj = j & 3;
            int kk = ks * 16 + ((jj >> 1) * 8) + 2 * (lane & 3) + (jj & 1);
            int nn = nb * 16 + (lane >> 2) + ((j >> 2) * 8);
            h2v[j] = __float2half_rn(w2[kk * 256 + nn]);
            h3v[j] = __float2half_rn(w3[kk * 256 + nn]);
        }
        *(uint4*)(gW2f + (size_t)frag * 512 + (size_t)lane * 16) = *(uint4*)h2v;
        *(uint4*)(gW3f + (size_t)frag * 512 + (size_t)lane * 16) = *(uint4*)h3v;
    }
    for (int u = idx; u < 16 * 4 * 32; u += stride) {       // W4 [256x20]
        int lane = u & 31, frag = u >> 5;
        int ks = frag >> 2, no = frag & 3;
        __half h[4];
        #pragma unroll
        for (int j = 0; j < 4; j++) {
            int kk = ks * 16 + ((j >> 1) * 8) + 2 * (lane & 3) + (j & 1);
            int nn = no * 8 + (lane >> 2);
            float v = (nn < 20) ? w4[kk * 20 + nn] : 0.0f;
            h[j] = __float2half_rn(v);
        }
        *(uint2*)(gW4f + (size_t)frag * 256 + (size_t)lane * 8) = *(uint2*)h;
    }
}

// ---------------- gemm k16-step: B via LDG, A via LDSM ----------------
__device__ __forceinline__ void step_ldg(uint32_t sb, int ks,
                                         const unsigned char* __restrict__ wf,
                                         int r0, int wn, int lane, float acc[2][8][4])
{
    const int lr = lane & 15, lh = lane >> 4;
    uint32_t b[4][4];
    #pragma unroll
    for (int ni2 = 0; ni2 < 4; ni2++)
        *(uint4*)b[ni2] = *(const uint4*)(wf
            + (size_t)((ks * 16 + wn * 4 + ni2) * 512) + (size_t)lane * 16);
    uint32_t a[2][4];
    #pragma unroll
    for (int mi = 0; mi < 2; mi++) {
        uint32_t ao = (uint32_t)(((r0 + 16 * mi + lr) * ASTR + ks * 16 + 8 * lh) * 2);
        ldm4(a[mi], sb + A_OFF + ao);
    }
    #pragma unroll
    for (int ni2 = 0; ni2 < 4; ni2++) {
        #pragma unroll
        for (int mi = 0; mi < 2; mi++) {
            mmah(acc[mi][2 * ni2],     a[mi], b[ni2]);
            mmah(acc[mi][2 * ni2 + 1], a[mi], b[ni2] + 2);
        }
    }
}

// epilogue: bias + tanh + fp16 scalar stores
__device__ __forceinline__ void epilogue(unsigned char* dsm, const float* bl,
                                         float acc[2][8][4], int r0, int c0, int lane)
{
    const int qr = lane >> 2, qc = (lane & 3) * 2;
    #pragma unroll
    for (int mi = 0; mi < 2; mi++) {
        #pragma unroll
        for (int ni = 0; ni < 8; ni++) {
            int col = c0 + 8 * ni + qc;
            float2 bb = *(const float2*)&bl[col];
            #pragma unroll
            for (int h = 0; h < 2; h++) {
                int row = r0 + 16 * mi + qr + 8 * h;
                float x0 = tanha(acc[mi][ni][2 * h]     + bb.x);
                float x1 = tanha(acc[mi][ni][2 * h + 1] + bb.y);
                *(uint32_t*)(dsm + A_OFF + (size_t)(row * ASTR + col) * 2) = packh2(x0, x1);
            }
        }
    }
}

#define ZERO_ACC(acc) { _Pragma("unroll") for (int mi = 0; mi < 2; mi++) \
    _Pragma("unroll") for (int ni = 0; ni < 8; ni++) \
    _Pragma("unroll") for (int q = 0; q < 4; q++) acc[mi][ni][q] = 0.0f; }

__global__ void __launch_bounds__(NTH, 2)
axiom_mma_kernel(const float* __restrict__ hist,
                 const float* __restrict__ b1, const float* __restrict__ b2,
                 const float* __restrict__ b3, const float* __restrict__ b4,
                 const float* __restrict__ p_alpha, const float* __restrict__ p_beta,
                 const float* __restrict__ p_gamma, const float* __restrict__ p_lam,
                 float* __restrict__ out, int B)
{
    extern __shared__ unsigned char dsm[];
    const uint32_t sb = smem_u32(dsm);
    float* sPhys = (float*)(dsm + PHYS_OFF);
    float* sBias = (float*)(dsm + BIAS_OFF);
    float* sB4   = (float*)(dsm + B4_OFF);

    const int tid  = threadIdx.x;
    const int lane = tid & 31;
    const int wrp  = tid >> 5;
    const int wm   = wrp & 1, wn = wrp >> 1;
    const int r0   = wm * 32, c0 = wn * 64;
    const int gRow0 = blockIdx.x * MT;
    const int gidx = (wrp >> 1) * 32 + lane;   // 0..127 within wm-group

    sBias[tid]       = b1[tid];
    sBias[256 + tid] = b2[tid];
    sBias[512 + tid] = b3[tid];
    if (tid < 32) sB4[tid] = (tid < NFORE) ? b4[tid] : 0.0f;

    // ---------- physics + build A1 (fp16), cols 0..47 ----------
    // tid 0..31 (warp 0, wm=0) -> rows 0..31 ; tid 32..63 (warp 1, wm=1) -> rows 32..63
    if (tid < MT) {
        const float a = 1.0f / (1.0f + expf(-p_alpha[0]));
        const float b = 1.0f / (1.0f + expf(-p_beta[0]));
        const float g = fabsf(p_gamma[0]);
        float h[NHIST];
        const float4* hp = (const float4*)(hist + (size_t)(gRow0 + tid) * NHIST);
        #pragma unroll
        for (int i = 0; i < 6; i++) {
            float4 v = hp[i];
            h[4*i] = v.x; h[4*i+1] = v.y; h[4*i+2] = v.z; h[4*i+3] = v.w;
        }
        float ph[NFORE];
        float d0=h[18],d1=h[19],d2=h[20],d3=h[21],d4=h[22],d5=h[23];
        float T = d5;
        #pragma unroll
        for (int i = 0; i < NFORE; i++) {
            float Tn = T - a*T - b*d0 - g*(T*T*T);
            d0=d1; d1=d2; d2=d3; d3=d4; d4=d5; d5=Tn;
            ph[i] = Tn; T = Tn;
            sPhys[tid * NFORE + i] = Tn;
        }
        #pragma unroll
        for (int j = 0; j < 24; j++) {
            int k0 = 2*j, k1 = 2*j+1;
            float v0 = (k0 < 24) ? h[k0] : (k0 < 44) ? ph[k0-24] : 0.0f;
            float v1 = (k1 < 24) ? h[k1] : (k1 < 44) ? ph[k1-24] : 0.0f;
            *(uint32_t*)(dsm + A_OFF + (size_t)(tid * ASTR + 2*j) * 2) = packh2(v0, v1);
        }
    }
    __syncthreads();   // ONLY global sync: bias + physics + A1 visible to all

    // T_physics out — group-partitioned rows (group g owns rows g*32..g*32+31)
    for (int i = gidx; i < 32 * NFORE; i += 128) {
        int row = r0 + i / NFORE, cc = i % NFORE;
        out[(size_t)B * NFORE + (size_t)(gRow0 + row) * NFORE + cc] = sPhys[row * NFORE + cc];
    }

    float acc[2][8][4];

    // ---------- layer 1: K=48 ----------
    ZERO_ACC(acc);
    #pragma unroll
    for (int ks = 0; ks < 3; ks++)
        step_ldg(sb, ks, gW1f, r0, wn, lane, acc);
    gbar(wm);                             // group's A1 reads done
    epilogue(dsm, sBias, acc, r0, c0, lane);
    gbar(wm);                             // group's A2 visible

    // ---------- layer 2: K=256 ----------
    ZERO_ACC(acc);
    #pragma unroll 4
    for (int ks = 0; ks < 16; ks++)
        step_ldg(sb, ks, gW2f, r0, wn, lane, acc);
    gbar(wm);
    epilogue(dsm, sBias + 256, acc, r0, c0, lane);
    gbar(wm);

    // ---------- layer 3: K=256 ----------
    ZERO_ACC(acc);
    #pragma unroll 4
    for (int ks = 0; ks < 16; ks++)
        step_ldg(sb, ks, gW3f, r0, wn, lane, acc);
    gbar(wm);
    epilogue(dsm, sBias + 512, acc, r0, c0, lane);
    gbar(wm);

    // ---------- layer 4: N=32 (20 valid), K=256 ----------
    {
        float a4[2][4];
        #pragma unroll
        for (int mi = 0; mi < 2; mi++)
            #pragma unroll
            for (int q = 0; q < 4; q++) a4[mi][q] = 0.0f;

        const int lr = lane & 15, lh = lane >> 4;
        #pragma unroll 4
        for (int ks = 0; ks < 16; ks++) {
            uint32_t b[2];
            *(uint2*)b = *(const uint2*)(gW4f
                + (size_t)((ks * 4 + wn) * 256) + (size_t)lane * 8);
            uint32_t a[2][4];
            #pragma unroll
            for (int mi = 0; mi < 2; mi++) {
                uint32_t ao = (uint32_t)(((r0 + 16 * mi + lr) * ASTR + ks * 16 + 8 * lh) * 2);
                ldm4(a[mi], sb + A_OFF + ao);
            }
            #pragma unroll
            for (int mi = 0; mi < 2; mi++) mmah(a4[mi], a[mi], b);
        }

        const float lam = 1.0f / (1.0f + expf(-p_lam[0]));
        const int qr = lane >> 2, qc = (lane & 3) * 2;
        const int c = wn * 8 + qc;
        if (c < NFORE) {
            float2 bb = *(const float2*)&sB4[c];
            #pragma unroll
            for (int mi = 0; mi < 2; mi++) {
                #pragma unroll
                for (int h = 0; h < 2; h++) {
                    int row = r0 + 16 * mi + qr + 8 * h;
                    float ts0 = a4[mi][2*h]     + bb.x;
                    float ts1 = a4[mi][2*h + 1] + bb.y;
                    float tp0 = sPhys[row * NFORE + c]     + lam * ts0;
                    float tp1 = sPhys[row * NFORE + c + 1] + lam * ts1;
                    size_t go = (size_t)(gRow0 + row) * NFORE + c;
                    *(float2*)&out[go] = make_float2(tp0, tp1);
                    *(float2*)&out[(size_t)2 * B * NFORE + go] = make_float2(ts0, ts1);
                }
            }
        }
    }
}

// ---------------- launch ----------------
extern "C" void kernel_launch(void* const* d_in, const int* in_sizes, int n_in,
                              void* d_out, int out_size)
{
    const float* hist  = (const float*)d_in[0];
    const float* w1    = (const float*)d_in[1];
    const float* b1    = (const float*)d_in[2];
    const float* w2    = (const float*)d_in[3];
    const float* b2    = (const float*)d_in[4];
    const float* w3    = (const float*)d_in[5];
    const float* b3    = (const float*)d_in[6];
    const float* w4    = (const float*)d_in[7];
    const float* b4    = (const float*)d_in[8];
    const float* alpha = (const float*)d_in[9];
    const float* beta  = (const float*)d_in[10];
    const float* gamma = (const float*)d_in[11];
    const float* lamx  = (const float*)d_in[13];
    float* out = (float*)d_out;

    const int B = in_sizes[0] / NHIST;
    const int nblocks = B / MT;

    prep_kernel<<<64, 256>>>(w1, w2, w3, w4);

    cudaFuncSetAttribute(axiom_mma_kernel,
                         cudaFuncAttributeMaxDynamicSharedMemorySize, SMEM_TOTAL);
    axiom_mma_kernel<<<nblocks, NTH, SMEM_TOTAL>>>(
        hist, b1, b2, b3, b4, alpha, beta, gamma, lamx, out, B);
}

// round 16
// speedup vs baseline: 1.0289x; 1.0289x over previous
#include <cuda_runtime.h>
#include <cuda_fp16.h>
#include <math.h>
#include <cstdint>

#define NHIST 24
#define NFORE 20
#define MT    64
#define NTH   256
#define ASTR  264     // sAct row stride (fp16 elems)

// ---------------- prepped weights: fragment-major fp16 ----------------
__device__ __align__(16) unsigned char gW1f[24576];    // 3 ks x 16 nb x 512
__device__ __align__(16) unsigned char gW2f[131072];   // 16 x 16 x 512
__device__ __align__(16) unsigned char gW3f[131072];
__device__ __align__(16) unsigned char gW4f[16384];    // 16 ks x 4 no x 256

// ---------------- SMEM layout (bytes) ----------------
#define A_OFF    0          // 64*264*2 = 33792
#define PHYS_OFF 33792      // 64*20*4 = 5120
#define BIAS_OFF 38912      // 768*4 = 3072
#define B4_OFF   41984      // 128
#define SMEM_TOTAL 42112

// ---------------- PTX helpers ----------------
__device__ __forceinline__ uint32_t smem_u32(const void* p) {
    uint32_t a;
    asm("{ .reg .u64 t; cvta.to.shared.u64 t, %1; cvt.u32.u64 %0, t; }" : "=r"(a) : "l"(p));
    return a;
}
__device__ __forceinline__ void ldm4(uint32_t r[4], uint32_t a) {
    asm volatile("ldmatrix.sync.aligned.m8n8.x4.shared.b16 {%0,%1,%2,%3}, [%4];"
                 : "=r"(r[0]), "=r"(r[1]), "=r"(r[2]), "=r"(r[3]) : "r"(a));
}
__device__ __forceinline__ void stm4(uint32_t a, uint32_t d0, uint32_t d1,
                                     uint32_t d2, uint32_t d3) {
    asm volatile("stmatrix.sync.aligned.m8n8.x4.shared.b16 [%0], {%1,%2,%3,%4};"
                 :: "r"(a), "r"(d0), "r"(d1), "r"(d2), "r"(d3) : "memory");
}
__device__ __forceinline__ void mmah(float c[4], const uint32_t a[4], const uint32_t b[2]) {
    asm volatile("mma.sync.aligned.m16n8k16.row.col.f32.f16.f16.f32 "
                 "{%0,%1,%2,%3}, {%4,%5,%6,%7}, {%8,%9}, {%0,%1,%2,%3};"
                 : "+f"(c[0]), "+f"(c[1]), "+f"(c[2]), "+f"(c[3])
                 : "r"(a[0]), "r"(a[1]), "r"(a[2]), "r"(a[3]), "r"(b[0]), "r"(b[1]));
}
__device__ __forceinline__ float tanha(float x) {
    float r; asm("tanh.approx.f32 %0, %1;" : "=f"(r) : "f"(x)); return r;
}
__device__ __forceinline__ uint32_t packh2(float lo, float hi) {
    __half2 t = __floats2half2_rn(lo, hi);
    return *reinterpret_cast<uint32_t*>(&t);
}

// ---------------- weight prep: fragment-major emit ----------------
__global__ void prep_kernel(const float* __restrict__ w1, const float* __restrict__ w2,
                            const float* __restrict__ w3, const float* __restrict__ w4)
{
    int idx = blockIdx.x * blockDim.x + threadIdx.x;
    int stride = gridDim.x * blockDim.x;

    for (int u = idx; u < 3 * 16 * 32; u += stride) {       // W1 [44x256]
        int lane = u & 31, frag = u >> 5;
        int ks = frag >> 4, nb = frag & 15;
        __half h[8];
        #pragma unroll
        for (int j = 0; j < 8; j++) {
            int jj = j & 3;
            int kk = ks * 16 + ((jj >> 1) * 8) + 2 * (lane & 3) + (jj & 1);
            int nn = nb * 16 + (lane >> 2) + ((j >> 2) * 8);
            float v = (kk < 44) ? w1[kk * 256 + nn] : 0.0f;
            h[j] = __float2half_rn(v);
        }
        *(uint4*)(gW1f + (size_t)frag * 512 + (size_t)lane * 16) = *(uint4*)h;
    }
    for (int u = idx; u < 16 * 16 * 32; u += stride) {      // W2, W3 [256x256]
        int lane = u & 31, frag = u >> 5;
        int ks = frag >> 4, nb = frag & 15;
        __half h2v[8], h3v[8];
        #pragma unroll
        for (int j = 0; j < 8; j++) {
            int jj = j & 3;
            int kk = ks * 16 + ((jj >> 1) * 8) + 2 * (lane & 3) + (jj & 1);
            int nn = nb * 16 + (lane >> 2) + ((j >> 2) * 8);
            h2v[j] = __float2half_rn(w2[kk * 256 + nn]);
            h3v[j] = __float2half_rn(w3[kk * 256 + nn]);
        }
        *(uint4*)(gW2f + (size_t)frag * 512 + (size_t)lane * 16) = *(uint4*)h2v;
        *(uint4*)(gW3f + (size_t)frag * 512 + (size_t)lane * 16) = *(uint4*)h3v;
    }
    for (int u = idx; u < 16 * 4 * 32; u += stride) {       // W4 [256x20]
        int lane = u & 31, frag = u >> 5;
        int ks = frag >> 2, no = frag & 3;
        __half h[4];
        #pragma unroll
        for (int j = 0; j < 4; j++) {
            int kk = ks * 16 + ((j >> 1) * 8) + 2 * (lane & 3) + (j & 1);
            int nn = no * 8 + (lane >> 2);
            float v = (nn < 20) ? w4[kk * 20 + nn] : 0.0f;
            h[j] = __float2half_rn(v);
        }
        *(uint2*)(gW4f + (size_t)frag * 256 + (size_t)lane * 8) = *(uint2*)h;
    }
}

// ---------------- gemm k16-step: B via LDG, A via LDSM ----------------
__device__ __forceinline__ void step_ldg(uint32_t sb, int ks,
                                         const unsigned char* __restrict__ wf,
                                         int r0, int wn, int lane, float acc[2][8][4])
{
    const int lr = lane & 15, lh = lane >> 4;
    uint32_t b[4][4];
    #pragma unroll
    for (int ni2 = 0; ni2 < 4; ni2++)
        *(uint4*)b[ni2] = *(const uint4*)(wf
            + (size_t)((ks * 16 + wn * 4 + ni2) * 512) + (size_t)lane * 16);
    uint32_t a[2][4];
    #pragma unroll
    for (int mi = 0; mi < 2; mi++) {
        uint32_t ao = (uint32_t)(((r0 + 16 * mi + lr) * ASTR + ks * 16 + 8 * lh) * 2);
        ldm4(a[mi], sb + A_OFF + ao);
    }
    #pragma unroll
    for (int ni2 = 0; ni2 < 4; ni2++) {
        #pragma unroll
        for (int mi = 0; mi < 2; mi++) {
            mmah(acc[mi][2 * ni2],     a[mi], b[ni2]);
            mmah(acc[mi][2 * ni2 + 1], a[mi], b[ni2] + 2);
        }
    }
}

// epilogue: bias + tanh + fp16, stored via stmatrix.x4 (conflict-free)
// data fragment = acc identity mapping; per ni: 4 matrices (mi,h) at rowbases r0+16mi+8h
__device__ __forceinline__ void epilogue(uint32_t sb, const float* bl,
                                         float acc[2][8][4], int r0, int c0, int lane)
{
    const int qc = (lane & 3) * 2;
    const int mat = lane >> 3, rr = lane & 7;          // this lane's address slot
    const int arow = r0 + 16 * (mat >> 1) + 8 * (mat & 1) + rr;
    #pragma unroll
    for (int ni = 0; ni < 8; ni++) {
        int col = c0 + 8 * ni + qc;
        float2 bb = *(const float2*)&bl[col];
        uint32_t d[4];
        // d[m2] = matrix (mi = m2>>1, h = m2&1)
        #pragma unroll
        for (int m2 = 0; m2 < 4; m2++) {
            int mi = m2 >> 1, h = m2 & 1;
            d[m2] = packh2(tanha(acc[mi][ni][2 * h]     + bb.x),
                           tanha(acc[mi][ni][2 * h + 1] + bb.y));
        }
        uint32_t ad = sb + A_OFF + (uint32_t)((arow * ASTR + c0 + 8 * ni) * 2);
        stm4(ad, d[0], d[1], d[2], d[3]);
    }
}

#define ZERO_ACC(acc) { _Pragma("unroll") for (int mi = 0; mi < 2; mi++) \
    _Pragma("unroll") for (int ni = 0; ni < 8; ni++) \
    _Pragma("unroll") for (int q = 0; q < 4; q++) acc[mi][ni][q] = 0.0f; }

__global__ void __launch_bounds__(NTH, 2)
axiom_mma_kernel(const float* __restrict__ hist,
                 const float* __restrict__ b1, const float* __restrict__ b2,
                 const float* __restrict__ b3, const float* __restrict__ b4,
                 const float* __restrict__ p_alpha, const float* __restrict__ p_beta,
                 const float* __restrict__ p_gamma, const float* __restrict__ p_lam,
                 float* __restrict__ out, int B)
{
    extern __shared__ unsigned char dsm[];
    const uint32_t sb = smem_u32(dsm);
    float* sPhys = (float*)(dsm + PHYS_OFF);
    float* sBias = (float*)(dsm + BIAS_OFF);
    float* sB4   = (float*)(dsm + B4_OFF);

    const int tid  = threadIdx.x;
    const int lane = tid & 31;
    const int wrp  = tid >> 5;
    const int wm   = wrp & 1, wn = wrp >> 1;
    const int r0   = wm * 32, c0 = wn * 64;
    const int gRow0 = blockIdx.x * MT;

    sBias[tid]       = b1[tid];
    sBias[256 + tid] = b2[tid];
    sBias[512 + tid] = b3[tid];
    if (tid < 32) sB4[tid] = (tid < NFORE) ? b4[tid] : 0.0f;

    // ---------- physics + build A1 (fp16), cols 0..47 ----------
    if (tid < MT) {
        const float a = 1.0f / (1.0f + expf(-p_alpha[0]));
        const float b = 1.0f / (1.0f + expf(-p_beta[0]));
        const float g = fabsf(p_gamma[0]);
        float h[NHIST];
        const float4* hp = (const float4*)(hist + (size_t)(gRow0 + tid) * NHIST);
        #pragma unroll
        for (int i = 0; i < 6; i++) {
            float4 v = hp[i];
            h[4*i] = v.x; h[4*i+1] = v.y; h[4*i+2] = v.z; h[4*i+3] = v.w;
        }
        float ph[NFORE];
        float d0=h[18],d1=h[19],d2=h[20],d3=h[21],d4=h[22],d5=h[23];
        float T = d5;
        #pragma unroll
        for (int i = 0; i < NFORE; i++) {
            float Tn = T - a*T - b*d0 - g*(T*T*T);
            d0=d1; d1=d2; d2=d3; d3=d4; d4=d5; d5=Tn;
            ph[i] = Tn; T = Tn;
            sPhys[tid * NFORE + i] = Tn;
        }
        #pragma unroll
        for (int j = 0; j < 24; j++) {
            int k0 = 2*j, k1 = 2*j+1;
            float v0 = (k0 < 24) ? h[k0] : (k0 < 44) ? ph[k0-24] : 0.0f;
            float v1 = (k1 < 24) ? h[k1] : (k1 < 44) ? ph[k1-24] : 0.0f;
            *(uint32_t*)(dsm + A_OFF + (size_t)(tid * ASTR + 2*j) * 2) = packh2(v0, v1);
        }
    }
    __syncthreads();

    // T_physics out
    for (int i = tid; i < MT * NFORE; i += NTH)
        out[(size_t)B * NFORE + (size_t)gRow0 * NFORE + i] = sPhys[i];

    float acc[2][8][4];

    // ---------- layer 1: K=48 ----------
    ZERO_ACC(acc);
    #pragma unroll
    for (int ks = 0; ks < 3; ks++)
        step_ldg(sb, ks, gW1f, r0, wn, lane, acc);
    __syncthreads();                      // A1 reads done
    epilogue(sb, sBias, acc, r0, c0, lane);
    __syncthreads();                      // A2 visible

    // ---------- layer 2: K=256 ----------
    ZERO_ACC(acc);
    #pragma unroll 4
    for (int ks = 0; ks < 16; ks++)
        step_ldg(sb, ks, gW2f, r0, wn, lane, acc);
    __syncthreads();
    epilogue(sb, sBias + 256, acc, r0, c0, lane);
    __syncthreads();

    // ---------- layer 3: K=256 ----------
    ZERO_ACC(acc);
    #pragma unroll 4
    for (int ks = 0; ks < 16; ks++)
        step_ldg(sb, ks, gW3f, r0, wn, lane, acc);
    __syncthreads();
    epilogue(sb, sBias + 512, acc, r0, c0, lane);
    __syncthreads();

    // ---------- layer 4: N=32 (20 valid), K=256 ----------
    {
        float a4[2][4];
        #pragma unroll
        for (int mi = 0; mi < 2; mi++)
            #pragma unroll
            for (int q = 0; q < 4; q++) a4[mi][q] = 0.0f;

        const int lr = lane & 15, lh = lane >> 4;
        #pragma unroll 4
        for (int ks = 0; ks < 16; ks++) {
            uint32_t b[2];
            *(uint2*)b = *(const uint2*)(gW4f
                + (size_t)((ks * 4 + wn) * 256) + (size_t)lane * 8);
            uint32_t a[2][4];
            #pragma unroll
            for (int mi = 0; mi < 2; mi++) {
                uint32_t ao = (uint32_t)(((r0 + 16 * mi + lr) * ASTR + ks * 16 + 8 * lh) * 2);
                ldm4(a[mi], sb + A_OFF + ao);
            }
            #pragma unroll
            for (int mi = 0; mi < 2; mi++) mmah(a4[mi], a[mi], b);
        }

        const float lam = 1.0f / (1.0f + expf(-p_lam[0]));
        const int qr = lane >> 2, qc = (lane & 3) * 2;
        const int c = wn * 8 + qc;
        if (c < NFORE) {
            float2 bb = *(const float2*)&sB4[c];
            #pragma unroll
            for (int mi = 0; mi < 2; mi++) {
                #pragma unroll
                for (int h = 0; h < 2; h++) {
                    int row = r0 + 16 * mi + qr + 8 * h;
                    float ts0 = a4[mi][2*h]     + bb.x;
                    float ts1 = a4[mi][2*h + 1] + bb.y;
                    float tp0 = sPhys[row * NFORE + c]     + lam * ts0;
                    float tp1 = sPhys[row * NFORE + c + 1] + lam * ts1;
                    size_t go = (size_t)(gRow0 + row) * NFORE + c;
                    *(float2*)&out[go] = make_float2(tp0, tp1);
                    *(float2*)&out[(size_t)2 * B * NFORE + go] = make_float2(ts0, ts1);
                }
            }
        }
    }
}

// ---------------- launch ----------------
extern "C" void kernel_launch(void* const* d_in, const int* in_sizes, int n_in,
                              void* d_out, int out_size)
{
    const float* hist  = (const float*)d_in[0];
    const float* w1    = (const float*)d_in[1];
    const float* b1    = (const float*)d_in[2];
    const float* w2    = (const float*)d_in[3];
    const float* b2    = (const float*)d_in[4];
    const float* w3    = (const float*)d_in[5];
    const float* b3    = (const float*)d_in[6];
    const float* w4    = (const float*)d_in[7];
    const float* b4    = (const float*)d_in[8];
    const float* alpha = (const float*)d_in[9];
    const float* beta  = (const float*)d_in[10];
    const float* gamma = (const float*)d_in[11];
    const float* lamx  = (const float*)d_in[13];
    float* out = (float*)d_out;

    const int B = in_sizes[0] / NHIST;
    const int nblocks = B / MT;

    prep_kernel<<<64, 256>>>(w1, w2, w3, w4);

    cudaFuncSetAttribute(axiom_mma_kernel,
                         cudaFuncAttributeMaxDynamicSharedMemorySize, SMEM_TOTAL);
    axiom_mma_kernel<<<nblocks, NTH, SMEM_TOTAL>>>(
        hist, b1, b2, b3, b4, alpha, beta, gamma, lamx, out, B);
}

// round 17
// speedup vs baseline: 1.0798x; 1.0495x over previous
#include <cuda_runtime.h>
#include <cuda_fp16.h>
#include <math.h>
#include <cstdint>

#define NHIST 24
#define NFORE 20
#define MT    32
#define NTH   128
#define ASTR  264     // sAct row stride (fp16 elems)

// ---------------- prepped weights: fragment-major fp16 ----------------
__device__ __align__(16) unsigned char gW1f[24576];    // 3 ks x 16 nb x 512
__device__ __align__(16) unsigned char gW2f[131072];   // 16 x 16 x 512
__device__ __align__(16) unsigned char gW3f[131072];
__device__ __align__(16) unsigned char gW4f[16384];    // 16 ks x 4 no x 256

// ---------------- SMEM layout (bytes) ----------------
#define A_OFF    0          // 32*264*2 = 16896
#define PHYS_OFF 16896      // 32*20*4 = 2560
#define BIAS_OFF 19456      // 768*4 = 3072
#define B4_OFF   22528      // 128
#define SMEM_TOTAL 22656

// ---------------- PTX helpers ----------------
__device__ __forceinline__ uint32_t smem_u32(const void* p) {
    uint32_t a;
    asm("{ .reg .u64 t; cvta.to.shared.u64 t, %1; cvt.u32.u64 %0, t; }" : "=r"(a) : "l"(p));
    return a;
}
__device__ __forceinline__ void ldm4(uint32_t r[4], uint32_t a) {
    asm volatile("ldmatrix.sync.aligned.m8n8.x4.shared.b16 {%0,%1,%2,%3}, [%4];"
                 : "=r"(r[0]), "=r"(r[1]), "=r"(r[2]), "=r"(r[3]) : "r"(a));
}
__device__ __forceinline__ void stm4(uint32_t a, uint32_t d0, uint32_t d1,
                                     uint32_t d2, uint32_t d3) {
    asm volatile("stmatrix.sync.aligned.m8n8.x4.shared.b16 [%0], {%1,%2,%3,%4};"
                 :: "r"(a), "r"(d0), "r"(d1), "r"(d2), "r"(d3) : "memory");
}
__device__ __forceinline__ void mmah(float c[4], const uint32_t a[4], const uint32_t b[2]) {
    asm volatile("mma.sync.aligned.m16n8k16.row.col.f32.f16.f16.f32 "
                 "{%0,%1,%2,%3}, {%4,%5,%6,%7}, {%8,%9}, {%0,%1,%2,%3};"
                 : "+f"(c[0]), "+f"(c[1]), "+f"(c[2]), "+f"(c[3])
                 : "r"(a[0]), "r"(a[1]), "r"(a[2]), "r"(a[3]), "r"(b[0]), "r"(b[1]));
}
__device__ __forceinline__ float tanha(float x) {
    float r; asm("tanh.approx.f32 %0, %1;" : "=f"(r) : "f"(x)); return r;
}
__device__ __forceinline__ uint32_t packh2(float lo, float hi) {
    __half2 t = __floats2half2_rn(lo, hi);
    return *reinterpret_cast<uint32_t*>(&t);
}

// ---------------- weight prep: fragment-major emit ----------------
__global__ void prep_kernel(const float* __restrict__ w1, const float* __restrict__ w2,
                            const float* __restrict__ w3, const float* __restrict__ w4)
{
    int idx = blockIdx.x * blockDim.x + threadIdx.x;
    int stride = gridDim.x * blockDim.x;

    for (int u = idx; u < 3 * 16 * 32; u += stride) {       // W1 [44x256]
        int lane = u & 31, frag = u >> 5;
        int ks = frag >> 4, nb = frag & 15;
        __half h[8];
        #pragma unroll
        for (int j = 0; j < 8; j++) {
            int jj = j & 3;
            int kk = ks * 16 + ((jj >> 1) * 8) + 2 * (lane & 3) + (jj & 1);
            int nn = nb * 16 + (lane >> 2) + ((j >> 2) * 8);
            float v = (kk < 44) ? w1[kk * 256 + nn] : 0.0f;
            h[j] = __float2half_rn(v);
        }
        *(uint4*)(gW1f + (size_t)frag * 512 + (size_t)lane * 16) = *(uint4*)h;
    }
    for (int u = idx; u < 16 * 16 * 32; u += stride) {      // W2, W3 [256x256]
        int lane = u & 31, frag = u >> 5;
        int ks = frag >> 4, nb = frag & 15;
        __half h2v[8], h3v[8];
        #pragma unroll
        for (int j = 0; j < 8; j++) {
            int jj = j & 3;
            int kk = ks * 16 + ((jj >> 1) * 8) + 2 * (lane & 3) + (jj & 1);
            int nn = nb * 16 + (lane >> 2) + ((j >> 2) * 8);
            h2v[j] = __float2half_rn(w2[kk * 256 + nn]);
            h3v[j] = __float2half_rn(w3[kk * 256 + nn]);
        }
        *(uint4*)(gW2f + (size_t)frag * 512 + (size_t)lane * 16) = *(uint4*)h2v;
        *(uint4*)(gW3f + (size_t)frag * 512 + (size_t)lane * 16) = *(uint4*)h3v;
    }
    for (int u = idx; u < 16 * 4 * 32; u += stride) {       // W4 [256x20]
        int lane = u & 31, frag = u >> 5;
        int ks = frag >> 2, no = frag & 3;
        __half h[4];
        #pragma unroll
        for (int j = 0; j < 4; j++) {
            int kk = ks * 16 + ((j >> 1) * 8) + 2 * (lane & 3) + (j & 1);
            int nn = no * 8 + (lane >> 2);
            float v = (nn < 20) ? w4[kk * 20 + nn] : 0.0f;
            h[j] = __float2half_rn(v);
        }
        *(uint2*)(gW4f + (size_t)frag * 256 + (size_t)lane * 8) = *(uint2*)h;
    }
}

// ---------------- gemm k16-step: B via LDG, A via LDSM (rows 0..31) ----------------
__device__ __forceinline__ void step_ldg(uint32_t sb, int ks,
                                         const unsigned char* __restrict__ wf,
                                         int wn, int lane, float acc[2][8][4])
{
    const int lr = lane & 15, lh = lane >> 4;
    uint32_t b[4][4];
    #pragma unroll
    for (int ni2 = 0; ni2 < 4; ni2++)
        *(uint4*)b[ni2] = *(const uint4*)(wf
            + (size_t)((ks * 16 + wn * 4 + ni2) * 512) + (size_t)lane * 16);
    uint32_t a[2][4];
    #pragma unroll
    for (int mi = 0; mi < 2; mi++) {
        uint32_t ao = (uint32_t)(((16 * mi + lr) * ASTR + ks * 16 + 8 * lh) * 2);
        ldm4(a[mi], sb + A_OFF + ao);
    }
    #pragma unroll
    for (int ni2 = 0; ni2 < 4; ni2++) {
        #pragma unroll
        for (int mi = 0; mi < 2; mi++) {
            mmah(acc[mi][2 * ni2],     a[mi], b[ni2]);
            mmah(acc[mi][2 * ni2 + 1], a[mi], b[ni2] + 2);
        }
    }
}

// epilogue: bias + tanh + fp16, stored via stmatrix.x4 (rows 0..31)
__device__ __forceinline__ void epilogue(uint32_t sb, const float* bl,
                                         float acc[2][8][4], int c0, int lane)
{
    const int qc = (lane & 3) * 2;
    const int mat = lane >> 3, rr = lane & 7;
    const int arow = 16 * (mat >> 1) + 8 * (mat & 1) + rr;
    #pragma unroll
    for (int ni = 0; ni < 8; ni++) {
        int col = c0 + 8 * ni + qc;
        float2 bb = *(const float2*)&bl[col];
        uint32_t d[4];
        #pragma unroll
        for (int m2 = 0; m2 < 4; m2++) {
            int mi = m2 >> 1, h = m2 & 1;
            d[m2] = packh2(tanha(acc[mi][ni][2 * h]     + bb.x),
                           tanha(acc[mi][ni][2 * h + 1] + bb.y));
        }
        uint32_t ad = sb + A_OFF + (uint32_t)((arow * ASTR + c0 + 8 * ni) * 2);
        stm4(ad, d[0], d[1], d[2], d[3]);
    }
}

#define ZERO_ACC(acc) { _Pragma("unroll") for (int mi = 0; mi < 2; mi++) \
    _Pragma("unroll") for (int ni = 0; ni < 8; ni++) \
    _Pragma("unroll") for (int q = 0; q < 4; q++) acc[mi][ni][q] = 0.0f; }

__global__ void __launch_bounds__(NTH, 4)
axiom_mma_kernel(const float* __restrict__ hist,
                 const float* __restrict__ b1, const float* __restrict__ b2,
                 const float* __restrict__ b3, const float* __restrict__ b4,
                 const float* __restrict__ p_alpha, const float* __restrict__ p_beta,
                 const float* __restrict__ p_gamma, const float* __restrict__ p_lam,
                 float* __restrict__ out, int B)
{
    extern __shared__ unsigned char dsm[];
    const uint32_t sb = smem_u32(dsm);
    float* sPhys = (float*)(dsm + PHYS_OFF);
    float* sBias = (float*)(dsm + BIAS_OFF);
    float* sB4   = (float*)(dsm + B4_OFF);

    const int tid  = threadIdx.x;
    const int lane = tid & 31;
    const int wn   = tid >> 5;            // 0..3
    const int c0   = wn * 64;
    const int gRow0 = blockIdx.x * MT;

    // biases (768 floats over 128 threads)
    #pragma unroll
    for (int i = 0; i < 2; i++) {
        int t = tid + i * 128;
        sBias[t]       = b1[t];
        sBias[256 + t] = b2[t];
        sBias[512 + t] = b3[t];
    }
    if (tid < 32) sB4[tid] = (tid < NFORE) ? b4[tid] : 0.0f;

    // ---------- physics + build A1 (fp16), cols 0..47, rows 0..31 ----------
    if (tid < MT) {
        const float a = 1.0f / (1.0f + expf(-p_alpha[0]));
        const float b = 1.0f / (1.0f + expf(-p_beta[0]));
        const float g = fabsf(p_gamma[0]);
        float h[NHIST];
        const float4* hp = (const float4*)(hist + (size_t)(gRow0 + tid) * NHIST);
        #pragma unroll
        for (int i = 0; i < 6; i++) {
            float4 v = hp[i];
            h[4*i] = v.x; h[4*i+1] = v.y; h[4*i+2] = v.z; h[4*i+3] = v.w;
        }
        float ph[NFORE];
        float d0=h[18],d1=h[19],d2=h[20],d3=h[21],d4=h[22],d5=h[23];
        float T = d5;
        #pragma unroll
        for (int i = 0; i < NFORE; i++) {
            float Tn = T - a*T - b*d0 - g*(T*T*T);
            d0=d1; d1=d2; d2=d3; d3=d4; d4=d5; d5=Tn;
            ph[i] = Tn; T = Tn;
            sPhys[tid * NFORE + i] = Tn;
        }
        #pragma unroll
        for (int j = 0; j < 24; j++) {
            int k0 = 2*j, k1 = 2*j+1;
            float v0 = (k0 < 24) ? h[k0] : (k0 < 44) ? ph[k0-24] : 0.0f;
            float v1 = (k1 < 24) ? h[k1] : (k1 < 44) ? ph[k1-24] : 0.0f;
            *(uint32_t*)(dsm + A_OFF + (size_t)(tid * ASTR + 2*j) * 2) = packh2(v0, v1);
        }
    }
    __syncthreads();

    // T_physics out (32*20 = 640 over 128 threads)
    for (int i = tid; i < MT * NFORE; i += NTH)
        out[(size_t)B * NFORE + (size_t)gRow0 * NFORE + i] = sPhys[i];

    float acc[2][8][4];

    // ---------- layer 1: K=48 ----------
    ZERO_ACC(acc);
    #pragma unroll
    for (int ks = 0; ks < 3; ks++)
        step_ldg(sb, ks, gW1f, wn, lane, acc);
    __syncthreads();                      // A1 reads done
    epilogue(sb, sBias, acc, c0, lane);
    __syncthreads();                      // A2 visible

    // ---------- layer 2: K=256 ----------
    ZERO_ACC(acc);
    #pragma unroll 4
    for (int ks = 0; ks < 16; ks++)
        step_ldg(sb, ks, gW2f, wn, lane, acc);
    __syncthreads();
    epilogue(sb, sBias + 256, acc, c0, lane);
    __syncthreads();

    // ---------- layer 3: K=256 ----------
    ZERO_ACC(acc);
    #pragma unroll 4
    for (int ks = 0; ks < 16; ks++)
        step_ldg(sb, ks, gW3f, wn, lane, acc);
    __syncthreads();
    epilogue(sb, sBias + 512, acc, c0, lane);
    __syncthreads();

    // ---------- layer 4: N=32 (20 valid), K=256 ----------
    {
        float a4[2][4];
        #pragma unroll
        for (int mi = 0; mi < 2; mi++)
            #pragma unroll
            for (int q = 0; q < 4; q++) a4[mi][q] = 0.0f;

        const int lr = lane & 15, lh = lane >> 4;
        #pragma unroll 4
        for (int ks = 0; ks < 16; ks++) {
            uint32_t b[2];
            *(uint2*)b = *(const uint2*)(gW4f
                + (size_t)((ks * 4 + wn) * 256) + (size_t)lane * 8);
            uint32_t a[2][4];
            #pragma unroll
            for (int mi = 0; mi < 2; mi++) {
                uint32_t ao = (uint32_t)(((16 * mi + lr) * ASTR + ks * 16 + 8 * lh) * 2);
                ldm4(a[mi], sb + A_OFF + ao);
            }
            #pragma unroll
            for (int mi = 0; mi < 2; mi++) mmah(a4[mi], a[mi], b);
        }

        const float lam = 1.0f / (1.0f + expf(-p_lam[0]));
        const int qr = lane >> 2, qc = (lane & 3) * 2;
        const int c = wn * 8 + qc;
        if (c < NFORE) {
            float2 bb = *(const float2*)&sB4[c];
            #pragma unroll
            for (int mi = 0; mi < 2; mi++) {
                #pragma unroll
                for (int h = 0; h < 2; h++) {
                    int row = 16 * mi + qr + 8 * h;
                    float ts0 = a4[mi][2*h]     + bb.x;
                    float ts1 = a4[mi][2*h + 1] + bb.y;
                    float tp0 = sPhys[row * NFORE + c]     + lam * ts0;
                    float tp1 = sPhys[row * NFORE + c + 1] + lam * ts1;
                    size_t go = (size_t)(gRow0 + row) * NFORE + c;
                    *(float2*)&out[go] = make_float2(tp0, tp1);
                    *(float2*)&out[(size_t)2 * B * NFORE + go] = make_float2(ts0, ts1);
                }
            }
        }
    }
}

// ---------------- launch ----------------
extern "C" void kernel_launch(void* const* d_in, const int* in_sizes, int n_in,
                              void* d_out, int out_size)
{
    const float* hist  = (const float*)d_in[0];
    const float* w1    = (const float*)d_in[1];
    const float* b1    = (const float*)d_in[2];
    const float* w2    = (const float*)d_in[3];
    const float* b2    = (const float*)d_in[4];
    const float* w3    = (const float*)d_in[5];
    const float* b3    = (const float*)d_in[6];
    const float* w4    = (const float*)d_in[7];
    const float* b4    = (const float*)d_in[8];
    const float* alpha = (const float*)d_in[9];
    const float* beta  = (const float*)d_in[10];
    const float* gamma = (const float*)d_in[11];
    const float* lamx  = (const float*)d_in[13];
    float* out = (float*)d_out;

    const int B = in_sizes[0] / NHIST;
    const int nblocks = B / MT;

    prep_kernel<<<64, 256>>>(w1, w2, w3, w4);

    cudaFuncSetAttribute(axiom_mma_kernel,
                         cudaFuncAttributeMaxDynamicSharedMemorySize, SMEM_TOTAL);
    axiom_mma_kernel<<<nblocks, NTH, SMEM_TOTAL>>>(
        hist, b1, b2, b3, b4, alpha, beta, gamma, lamx, out, B);
}